// round 4
// baseline (speedup 1.0000x reference)
#include <cuda_runtime.h>

// EPN_layer: antisymmetric pairwise-MLP electron/charge update.
// Shapes: B=8, N=256, DH=32, DX=3, DQ=1, DE=8, H1=H2=32, DIN=80.
//
// Factorization: layer1 splits into per-atom projections
//   A*[a] = inp_atom[a] @ W1[0:36]  + b1     (inp_atom = [x, h, q], 36 feats)
//   Bt[a] = inp_atom[a] @ W1[36:72]
//   E[i,j] = e[i,j] @ W1[72:80]              (shared by ij and ji directions)
//   z1_ij = relu(A*_i + Bt_j + E),  z1_ji = relu(A*_j + Bt_i + E)
// b3 cancels in (elec_ij - elec_ji).

#define BB 8
#define NN 256
#define H1C 32
#define H2C 32
#define DEC 8
#define NATOMS (BB * NN)   // 2048

// Scratch (no allocations allowed in kernel_launch): per-atom projections.
__device__ float g_A [NATOMS * H1C];   // A* = inp @ W1a + b1
__device__ float g_Bt[NATOMS * H1C];   // Bt = inp @ W1b

// ---------------------------------------------------------------------------
// Phase 0: per-atom projections. One thread per (atom, which, k).
// Warp = (atom, which): inp reads broadcast, W reads coalesced over k.
// ---------------------------------------------------------------------------
__global__ void atom_proj_kernel(const float* __restrict__ h,
                                 const float* __restrict__ x,
                                 const float* __restrict__ q,
                                 const float* __restrict__ W1,
                                 const float* __restrict__ b1)
{
    int id = blockIdx.x * blockDim.x + threadIdx.x;   // atom*64 + which*32 + k
    if (id >= NATOMS * 64) return;
    int k     = id & 31;
    int which = (id >> 5) & 1;     // 0 -> A*, 1 -> Bt
    int atom  = id >> 6;

    const float* Wcol = W1 + (which ? 36 * H1C : 0);

    float acc = which ? 0.0f : b1[k];
    // inp_atom = [x(3), h(32), q(1)]
    #pragma unroll
    for (int f = 0; f < 3; ++f)
        acc = fmaf(x[atom * 3 + f], Wcol[f * H1C + k], acc);
    #pragma unroll
    for (int f = 0; f < 32; ++f)
        acc = fmaf(h[atom * 32 + f], Wcol[(3 + f) * H1C + k], acc);
    acc = fmaf(q[atom], Wcol[35 * H1C + k], acc);

    if (which) g_Bt[atom * H1C + k] = acc;
    else       g_A [atom * H1C + k] = acc;
}

// ---------------------------------------------------------------------------
// Phase 1: pair kernel. Block = (b,i) row; thread = j. Both MLP directions
// computed per thread with a fused dual-accumulator layer-2 loop sharing
// every W2 shared-memory load. Block reduction -> out[b,i].
// ---------------------------------------------------------------------------
__global__ __launch_bounds__(256, 2)
void pair_kernel(const float* __restrict__ e,
                 const float* __restrict__ mask,
                 const float* __restrict__ q,
                 const float* __restrict__ W1,
                 const float* __restrict__ W2,
                 const float* __restrict__ b2,
                 const float* __restrict__ W3,
                 float* __restrict__ out)
{
    __shared__ float sW2T[H2C][H1C];   // sW2T[k][m] = W2[m][k]
    __shared__ float sW1c[DEC][H1C];   // e-projection weights (W1 rows 72..79)
    __shared__ float sW3[H2C];
    __shared__ float sB2[H2C];
    __shared__ float sAi[H1C];
    __shared__ float sBi[H1C];
    __shared__ float sred[8];

    const int bi = blockIdx.x;        // b*256 + i
    const int j  = threadIdx.x;
    const int b  = bi >> 8;

    // Cooperative shared loads
    for (int idx = threadIdx.x; idx < H1C * H2C; idx += 256) {
        int m = idx >> 5, k = idx & 31;
        sW2T[k][m] = W2[m * H2C + k];
    }
    if (threadIdx.x < DEC * H1C) {
        int m = threadIdx.x >> 5, k = threadIdx.x & 31;
        sW1c[m][k] = W1[(72 + m) * H1C + k];
    }
    if (threadIdx.x < H2C) {
        sW3[threadIdx.x] = W3[threadIdx.x];
        sB2[threadIdx.x] = b2[threadIdx.x];
    }
    if (threadIdx.x < H1C) {
        sAi[threadIdx.x] = g_A [bi * H1C + threadIdx.x];
        sBi[threadIdx.x] = g_Bt[bi * H1C + threadIdx.x];
    }
    __syncthreads();

    // --- per-pair inputs ---
    const float4* ep = reinterpret_cast<const float4*>(e + ((size_t)bi * NN + j) * DEC);
    float4 e0 = ep[0], e1 = ep[1];
    float ev[8] = {e0.x, e0.y, e0.z, e0.w, e1.x, e1.y, e1.z, e1.w};

    float emax = ev[0];
    #pragma unroll
    for (int m = 1; m < 8; ++m) emax = fmaxf(emax, ev[m]);
    const float mval  = mask[(size_t)bi * NN + j];
    const float scale = (emax > 1e-5f) ? 0.5f * mval : 0.0f;

    // --- E = e @ W1c (shared between both directions) ---
    float zi[H1C];
    #pragma unroll
    for (int k = 0; k < H1C; ++k) zi[k] = 0.0f;
    #pragma unroll
    for (int m = 0; m < 8; ++m) {
        float em = ev[m];
        #pragma unroll
        for (int k = 0; k < H1C; ++k)
            zi[k] = fmaf(em, sW1c[m][k], zi[k]);
    }

    // --- z1 for both directions (zi := relu(A*_i + Bt_j + E), zj likewise) ---
    const float* __restrict__ Aj = g_A  + (((size_t)b << 8) + j) * H1C;
    const float* __restrict__ Bj = g_Bt + (((size_t)b << 8) + j) * H1C;
    float zj[H1C];
    #pragma unroll
    for (int k = 0; k < H1C; ++k) {
        float E = zi[k];
        zi[k] = fmaxf(sAi[k] + Bj[k] + E, 0.0f);
        zj[k] = fmaxf(Aj[k] + sBi[k] + E, 0.0f);
    }

    // --- layers 2+3, both directions fused (share every W2 load) ---
    float s_ij = 0.0f, s_ji = 0.0f;
    #pragma unroll 4
    for (int k = 0; k < H2C; ++k) {
        float t1 = sB2[k];
        float t2 = t1;
        #pragma unroll
        for (int m = 0; m < H1C; ++m) {
            float w = sW2T[k][m];
            t1 = fmaf(zi[m], w, t1);
            t2 = fmaf(zj[m], w, t2);
        }
        float w3 = sW3[k];
        s_ij = fmaf(fmaxf(t1, 0.0f), w3, s_ij);
        s_ji = fmaf(fmaxf(t2, 0.0f), w3, s_ji);
    }
    // b3 cancels in the difference
    float val = scale * (s_ij - s_ji);

    // --- block reduction over j ---
    #pragma unroll
    for (int off = 16; off > 0; off >>= 1)
        val += __shfl_xor_sync(0xffffffffu, val, off);
    if ((threadIdx.x & 31) == 0) sred[threadIdx.x >> 5] = val;
    __syncthreads();
    if (threadIdx.x == 0) {
        float t = 0.0f;
        #pragma unroll
        for (int w = 0; w < 8; ++w) t += sred[w];
        out[bi] = q[bi] + t;
    }
}

// ---------------------------------------------------------------------------
// Launch. Inputs (metadata order): h, e, x, q, mask, W1, b1, W2, b2, W3, b3.
// ---------------------------------------------------------------------------
extern "C" void kernel_launch(void* const* d_in, const int* in_sizes, int n_in,
                              void* d_out, int out_size)
{
    const float* h    = (const float*)d_in[0];
    const float* e    = (const float*)d_in[1];
    const float* x    = (const float*)d_in[2];
    const float* q    = (const float*)d_in[3];
    const float* mask = (const float*)d_in[4];
    const float* W1   = (const float*)d_in[5];
    const float* b1   = (const float*)d_in[6];
    const float* W2   = (const float*)d_in[7];
    const float* b2   = (const float*)d_in[8];
    const float* W3   = (const float*)d_in[9];
    // d_in[10] = b3: cancels in elec_ij - elec_ji, unused.
    float* out = (float*)d_out;

    atom_proj_kernel<<<(NATOMS * 64 + 255) / 256, 256>>>(h, x, q, W1, b1);
    pair_kernel<<<NATOMS, 256>>>(e, mask, q, W1, W2, b2, W3, out);
}

// round 5
// speedup vs baseline: 1.9933x; 1.9933x over previous
#include <cuda_runtime.h>

// EPN_layer: antisymmetric pairwise-MLP charge update.
// B=8, N=256, DH=32, DX=3, DQ=1, DE=8, H1=H2=32, DIN=80.
//
// Factorization (layer1 splits by input blocks):
//   A*[a] = inp_atom[a] @ W1[0:36] + b1,  Bt[a] = inp_atom[a] @ W1[36:72]
//   E[i,j] = e[i,j] @ W1[72:80]   (shared by both directions)
//   z1_ij = relu(A*_i + Bt_j + E), z1_ji = relu(A*_j + Bt_i + E); b3 cancels.
//
// R4 changes vs R0:
//  * g_A/g_Bt stored TRANSPOSED [k][atom] -> coalesced Aj/Bj loads
//    (was 32 L1 wavefronts per LDG.32; now 1).
//  * layer-2 dual-direction loop packed into fma.rn.f32x2 against a
//    duplicated-weight shared table read via LDS.128.
//  * E-projection packed into f32x2 over k-pairs.

#define BB 8
#define NN 256
#define H1C 32
#define H2C 32
#define DEC 8
#define NATOMS (BB * NN)   // 2048

// Transposed per-atom projections: [k][atom]
__device__ float g_AT[H1C * NATOMS];
__device__ float g_BT[H1C * NATOMS];

typedef unsigned long long u64;

__device__ __forceinline__ u64 dup2(float w) {
    u64 r; asm("mov.b64 %0, {%1, %1};" : "=l"(r) : "f"(w)); return r;
}
__device__ __forceinline__ u64 pk2(float lo, float hi) {
    u64 r; asm("mov.b64 %0, {%1, %2};" : "=l"(r) : "f"(lo), "f"(hi)); return r;
}
__device__ __forceinline__ void upk2(float& lo, float& hi, u64 v) {
    asm("mov.b64 {%0, %1}, %2;" : "=f"(lo), "=f"(hi) : "l"(v));
}
__device__ __forceinline__ u64 fma2(u64 a, u64 b, u64 c) {
    u64 d; asm("fma.rn.f32x2 %0, %1, %2, %3;" : "=l"(d) : "l"(a), "l"(b), "l"(c));
    return d;
}

// ---------------------------------------------------------------------------
// Phase 0: per-atom projections (tiny: 2048 atoms). Output transposed.
// ---------------------------------------------------------------------------
__global__ void atom_proj_kernel(const float* __restrict__ h,
                                 const float* __restrict__ x,
                                 const float* __restrict__ q,
                                 const float* __restrict__ W1,
                                 const float* __restrict__ b1)
{
    int id = blockIdx.x * blockDim.x + threadIdx.x;   // atom*64 + which*32 + k
    if (id >= NATOMS * 64) return;
    int k     = id & 31;
    int which = (id >> 5) & 1;     // 0 -> A*, 1 -> Bt
    int atom  = id >> 6;

    const float* Wcol = W1 + (which ? 36 * H1C : 0);

    float acc = which ? 0.0f : b1[k];
    #pragma unroll
    for (int f = 0; f < 3; ++f)
        acc = fmaf(x[atom * 3 + f], Wcol[f * H1C + k], acc);
    #pragma unroll
    for (int f = 0; f < 32; ++f)
        acc = fmaf(h[atom * 32 + f], Wcol[(3 + f) * H1C + k], acc);
    acc = fmaf(q[atom], Wcol[35 * H1C + k], acc);

    if (which) g_BT[k * NATOMS + atom] = acc;
    else       g_AT[k * NATOMS + atom] = acc;
}

// ---------------------------------------------------------------------------
// Phase 1: pair kernel. Block = (b,i); thread = j. Dual-direction MLP with
// packed f32x2 math; coalesced Aj/Bj; block reduce -> out[b,i].
// ---------------------------------------------------------------------------
__global__ __launch_bounds__(256, 2)
void pair_kernel(const float* __restrict__ e,
                 const float* __restrict__ mask,
                 const float* __restrict__ q,
                 const float* __restrict__ W1,
                 const float* __restrict__ W2,
                 const float* __restrict__ b2,
                 const float* __restrict__ W3,
                 float* __restrict__ out)
{
    __shared__ alignas(16) u64   sW2d[H2C][H1C];  // [k][m] = (W2[m][k], W2[m][k])
    __shared__ alignas(16) float sW1c[DEC][H1C];  // e-projection (W1 rows 72..79)
    __shared__ float sW3[H2C];
    __shared__ float sB2[H2C];
    __shared__ float sAi[H1C];
    __shared__ float sBi[H1C];
    __shared__ float sred[8];

    const int bi = blockIdx.x;        // b*256 + i
    const int j  = threadIdx.x;
    const int atomBase = bi & ~(NN - 1);   // b*256

    // Cooperative shared fills
    #pragma unroll
    for (int t = 0; t < 4; ++t) {
        int idx = threadIdx.x + t * 256;        // over 1024 = 32x32
        int m = idx >> 5, k = idx & 31;
        unsigned int w = __float_as_uint(W2[m * H2C + k]);
        sW2d[k][m] = (u64)w | ((u64)w << 32);
    }
    if (threadIdx.x < DEC * H1C) {
        int m = threadIdx.x >> 5, k = threadIdx.x & 31;
        sW1c[m][k] = W1[(72 + m) * H1C + k];
    }
    if (threadIdx.x < H2C) {
        sW3[threadIdx.x] = W3[threadIdx.x];
        sB2[threadIdx.x] = b2[threadIdx.x];
        sAi[threadIdx.x] = g_AT[threadIdx.x * NATOMS + bi];
        sBi[threadIdx.x] = g_BT[threadIdx.x * NATOMS + bi];
    }
    __syncthreads();

    // --- per-pair inputs ---
    const float4* ep = reinterpret_cast<const float4*>(e + ((size_t)bi * NN + j) * DEC);
    float4 e0 = ep[0], e1 = ep[1];
    float ev[8] = {e0.x, e0.y, e0.z, e0.w, e1.x, e1.y, e1.z, e1.w};

    float emax = ev[0];
    #pragma unroll
    for (int m = 1; m < 8; ++m) emax = fmaxf(emax, ev[m]);
    const float mval  = mask[(size_t)bi * NN + j];
    const float scale = (emax > 1e-5f) ? 0.5f * mval : 0.0f;

    // --- E = e @ W1c, packed over k-pairs: Epk[kk] = (E[2kk], E[2kk+1]) ---
    u64 Epk[H1C / 2];
    #pragma unroll
    for (int kk = 0; kk < 16; ++kk) Epk[kk] = 0ull;
    #pragma unroll
    for (int m = 0; m < 8; ++m) {
        u64 em2 = dup2(ev[m]);
        const u64* wrow = reinterpret_cast<const u64*>(&sW1c[m][0]);
        #pragma unroll
        for (int kk = 0; kk < 16; ++kk)
            Epk[kk] = fma2(em2, wrow[kk], Epk[kk]);
    }

    // --- z1 both directions, packed zd[k] = (z_ij[k], z_ji[k]) ---
    const float* __restrict__ AjT = g_AT + atomBase + j;   // stride NATOMS over k
    const float* __restrict__ BjT = g_BT + atomBase + j;
    u64 zd[H1C];
    #pragma unroll
    for (int kk = 0; kk < 16; ++kk) {
        int k0 = 2 * kk, k1 = 2 * kk + 1;
        float E0, E1; upk2(E0, E1, Epk[kk]);
        float aj0 = AjT[(size_t)k0 * NATOMS], aj1 = AjT[(size_t)k1 * NATOMS];
        float bj0 = BjT[(size_t)k0 * NATOMS], bj1 = BjT[(size_t)k1 * NATOMS];
        float zi0 = fmaxf(sAi[k0] + bj0 + E0, 0.0f);
        float zj0 = fmaxf(aj0 + sBi[k0] + E0, 0.0f);
        float zi1 = fmaxf(sAi[k1] + bj1 + E1, 0.0f);
        float zj1 = fmaxf(aj1 + sBi[k1] + E1, 0.0f);
        zd[k0] = pk2(zi0, zj0);
        zd[k1] = pk2(zi1, zj1);
    }

    // --- layers 2+3, both directions in one packed accumulator ---
    float s_ij = 0.0f, s_ji = 0.0f;
    #pragma unroll 8
    for (int k = 0; k < H2C; ++k) {
        u64 acc = dup2(sB2[k]);
        const ulonglong2* wrow = reinterpret_cast<const ulonglong2*>(&sW2d[k][0]);
        #pragma unroll
        for (int m2 = 0; m2 < 16; ++m2) {
            ulonglong2 w = wrow[m2];                 // LDS.128: two dup'd weights
            acc = fma2(zd[2 * m2],     w.x, acc);
            acc = fma2(zd[2 * m2 + 1], w.y, acc);
        }
        float t1, t2; upk2(t1, t2, acc);
        float w3 = sW3[k];
        s_ij = fmaf(fmaxf(t1, 0.0f), w3, s_ij);
        s_ji = fmaf(fmaxf(t2, 0.0f), w3, s_ji);
    }
    float val = scale * (s_ij - s_ji);   // b3 cancels

    // --- block reduction over j ---
    #pragma unroll
    for (int off = 16; off > 0; off >>= 1)
        val += __shfl_xor_sync(0xffffffffu, val, off);
    if ((threadIdx.x & 31) == 0) sred[threadIdx.x >> 5] = val;
    __syncthreads();
    if (threadIdx.x == 0) {
        float t = 0.0f;
        #pragma unroll
        for (int w = 0; w < 8; ++w) t += sred[w];
        out[bi] = q[bi] + t;
    }
}

// ---------------------------------------------------------------------------
// Launch. Inputs (metadata order): h, e, x, q, mask, W1, b1, W2, b2, W3, b3.
// ---------------------------------------------------------------------------
extern "C" void kernel_launch(void* const* d_in, const int* in_sizes, int n_in,
                              void* d_out, int out_size)
{
    const float* h    = (const float*)d_in[0];
    const float* e    = (const float*)d_in[1];
    const float* x    = (const float*)d_in[2];
    const float* q    = (const float*)d_in[3];
    const float* mask = (const float*)d_in[4];
    const float* W1   = (const float*)d_in[5];
    const float* b1   = (const float*)d_in[6];
    const float* W2   = (const float*)d_in[7];
    const float* b2   = (const float*)d_in[8];
    const float* W3   = (const float*)d_in[9];
    // d_in[10] = b3: cancels in elec_ij - elec_ji.
    float* out = (float*)d_out;

    atom_proj_kernel<<<(NATOMS * 64 + 255) / 256, 256>>>(h, x, q, W1, b1);
    pair_kernel<<<NATOMS, 256>>>(e, mask, q, W1, W2, b2, W3, out);
}

// round 6
// speedup vs baseline: 2.9158x; 1.4628x over previous
#include <cuda_runtime.h>

// EPN_layer: antisymmetric pairwise-MLP charge update.
// B=8, N=256, DH=32, DX=3, DQ=1, DE=8, H1=H2=32, DIN=80.
//
// Factorization (layer1 splits by input blocks):
//   A*[a] = inp_atom[a] @ W1[0:36] + b1,  Bt[a] = inp_atom[a] @ W1[36:72]
//   E[i,j] = e[i,j] @ W1[72:80]   (shared by both directions)
//   z1_ij = relu(A*_i + Bt_j + E), z1_ji = relu(A*_j + Bt_i + E); b3 cancels.
//
// R5 changes vs R4 (which was LDS-wavefront-bound, L1=87%):
//  * f32x2 packing re-paired: pack consecutive outputs (k,k+1) instead of the
//    two directions -> weight pairs are contiguous in the W2 row, so shared
//    weights are loaded RAW via LDS.128 (no duplicated-weight table; layer-2
//    LDS.128 count 512 -> 256). z[m] is duplicated in registers (alu movs).
//  * E-projection restructured the same way (LDS.128 instead of LDS.64).
//  * A*/Bt merged into one interleaved float2 table [k][atom] (32 LDG.64).

#define BB 8
#define NN 256
#define H1C 32
#define H2C 32
#define DEC 8
#define NATOMS (BB * NN)   // 2048

// Interleaved per-atom projections, transposed: g_ABT[k*NATOMS+atom] = (A*, Bt)
__device__ float2 g_ABT[H1C * NATOMS];

typedef unsigned long long u64;

__device__ __forceinline__ u64 dup2(float w) {
    u64 r; asm("mov.b64 %0, {%1, %1};" : "=l"(r) : "f"(w)); return r;
}
__device__ __forceinline__ void upk2(float& lo, float& hi, u64 v) {
    asm("mov.b64 {%0, %1}, %2;" : "=f"(lo), "=f"(hi) : "l"(v));
}
__device__ __forceinline__ u64 fma2(u64 a, u64 b, u64 c) {
    u64 d; asm("fma.rn.f32x2 %0, %1, %2, %3;" : "=l"(d) : "l"(a), "l"(b), "l"(c));
    return d;
}

// ---------------------------------------------------------------------------
// Phase 0: per-atom projections (2048 atoms x 32 k). One thread computes both
// A* and Bt for (atom,k); warp = one atom (h reads broadcast, W coalesced).
// ---------------------------------------------------------------------------
__global__ void atom_proj_kernel(const float* __restrict__ h,
                                 const float* __restrict__ x,
                                 const float* __restrict__ q,
                                 const float* __restrict__ W1,
                                 const float* __restrict__ b1)
{
    int id = blockIdx.x * blockDim.x + threadIdx.x;   // atom*32 + k
    if (id >= NATOMS * H1C) return;
    int k    = id & 31;
    int atom = id >> 5;

    float a  = b1[k];
    float bt = 0.0f;
    #pragma unroll
    for (int f = 0; f < 3; ++f) {
        float xv = x[atom * 3 + f];
        a  = fmaf(xv, W1[f * H1C + k],        a);
        bt = fmaf(xv, W1[(36 + f) * H1C + k], bt);
    }
    #pragma unroll
    for (int f = 0; f < 32; ++f) {
        float hv = h[atom * 32 + f];
        a  = fmaf(hv, W1[(3 + f) * H1C + k],  a);
        bt = fmaf(hv, W1[(39 + f) * H1C + k], bt);
    }
    float qv = q[atom];
    a  = fmaf(qv, W1[35 * H1C + k], a);
    bt = fmaf(qv, W1[71 * H1C + k], bt);

    g_ABT[k * NATOMS + atom] = make_float2(a, bt);
}

// ---------------------------------------------------------------------------
// Phase 1: pair kernel. Block = (b,i); thread = j.
// ---------------------------------------------------------------------------
__global__ __launch_bounds__(256, 2)
void pair_kernel(const float* __restrict__ e,
                 const float* __restrict__ mask,
                 const float* __restrict__ q,
                 const float* __restrict__ W1,
                 const float* __restrict__ W2,
                 const float* __restrict__ b2,
                 const float* __restrict__ W3,
                 float* __restrict__ out)
{
    __shared__ alignas(16) float sW2[H1C][H2C];   // raw W2 [m][k]
    __shared__ alignas(16) float sW1c[DEC][H1C];  // e-projection (W1 rows 72..79)
    __shared__ alignas(16) float sB2[H2C];
    __shared__ float sW3[H2C];
    __shared__ float sAi[H1C];
    __shared__ float sBi[H1C];
    __shared__ float sred[8];

    const int bi = blockIdx.x;             // b*256 + i
    const int j  = threadIdx.x;
    const int atomBase = bi & ~(NN - 1);   // b*256

    // Cooperative shared fills
    #pragma unroll
    for (int t = 0; t < 4; ++t) {
        int idx = threadIdx.x + t * 256;   // 1024 = 32x32
        sW2[idx >> 5][idx & 31] = W2[idx];
    }
    if (threadIdx.x < DEC * H1C)
        sW1c[threadIdx.x >> 5][threadIdx.x & 31] = W1[72 * H1C + threadIdx.x];
    if (threadIdx.x < H2C) {
        sW3[threadIdx.x] = W3[threadIdx.x];
        sB2[threadIdx.x] = b2[threadIdx.x];
        float2 ab = g_ABT[threadIdx.x * NATOMS + bi];
        sAi[threadIdx.x] = ab.x;
        sBi[threadIdx.x] = ab.y;
    }
    __syncthreads();

    // --- per-pair inputs ---
    const float4* ep = reinterpret_cast<const float4*>(e + ((size_t)bi * NN + j) * DEC);
    float4 e0 = ep[0], e1 = ep[1];
    float ev[8] = {e0.x, e0.y, e0.z, e0.w, e1.x, e1.y, e1.z, e1.w};

    float emax = ev[0];
    #pragma unroll
    for (int m = 1; m < 8; ++m) emax = fmaxf(emax, ev[m]);
    const float mval  = mask[(size_t)bi * NN + j];
    const float scale = (emax > 1e-5f) ? 0.5f * mval : 0.0f;

    // --- E = e @ W1c, packed over consecutive k-pairs via raw LDS.128 ---
    u64 Epk[H1C / 2];
    #pragma unroll
    for (int kk = 0; kk < 16; ++kk) Epk[kk] = 0ull;
    #pragma unroll
    for (int m = 0; m < 8; ++m) {
        u64 em2 = dup2(ev[m]);
        const ulonglong2* wrow = reinterpret_cast<const ulonglong2*>(&sW1c[m][0]);
        #pragma unroll
        for (int f4 = 0; f4 < 8; ++f4) {
            ulonglong2 w = wrow[f4];       // LDS.128: pairs (4f4,4f4+1),(4f4+2,4f4+3)
            Epk[2 * f4]     = fma2(em2, w.x, Epk[2 * f4]);
            Epk[2 * f4 + 1] = fma2(em2, w.y, Epk[2 * f4 + 1]);
        }
    }

    // --- z1 both directions (scalar registers; coalesced float2 LDG) ---
    const float2* __restrict__ ABj = g_ABT;   // index k*NATOMS + atomBase + j
    float z_ij[H1C], z_ji[H1C];
    #pragma unroll
    for (int kk = 0; kk < 16; ++kk) {
        int k0 = 2 * kk, k1 = k0 + 1;
        float E0, E1; upk2(E0, E1, Epk[kk]);
        float2 ab0 = ABj[(size_t)k0 * NATOMS + atomBase + j];
        float2 ab1 = ABj[(size_t)k1 * NATOMS + atomBase + j];
        z_ij[k0] = fmaxf(sAi[k0] + ab0.y + E0, 0.0f);
        z_ji[k0] = fmaxf(ab0.x + sBi[k0] + E0, 0.0f);
        z_ij[k1] = fmaxf(sAi[k1] + ab1.y + E1, 0.0f);
        z_ji[k1] = fmaxf(ab1.x + sBi[k1] + E1, 0.0f);
    }

    // --- layers 2+3: k split in two halves (register pressure), both
    //     directions share every raw W2 row load ---
    float s_ij = 0.0f, s_ji = 0.0f;
    #pragma unroll
    for (int half = 0; half < 2; ++half) {
        u64 accI[8], accJ[8];
        const u64* b2p = reinterpret_cast<const u64*>(&sB2[half * 16]);
        #pragma unroll
        for (int kk = 0; kk < 8; ++kk) { accI[kk] = b2p[kk]; accJ[kk] = b2p[kk]; }

        #pragma unroll
        for (int m = 0; m < H1C; ++m) {
            const ulonglong2* wrow =
                reinterpret_cast<const ulonglong2*>(&sW2[m][half * 16]);
            u64 zi2 = dup2(z_ij[m]);
            u64 zj2 = dup2(z_ji[m]);
            #pragma unroll
            for (int f4 = 0; f4 < 4; ++f4) {
                ulonglong2 w = wrow[f4];   // LDS.128: 4 consecutive W2[m][k]
                accI[2 * f4]     = fma2(zi2, w.x, accI[2 * f4]);
                accJ[2 * f4]     = fma2(zj2, w.x, accJ[2 * f4]);
                accI[2 * f4 + 1] = fma2(zi2, w.y, accI[2 * f4 + 1]);
                accJ[2 * f4 + 1] = fma2(zj2, w.y, accJ[2 * f4 + 1]);
            }
        }
        #pragma unroll
        for (int kk = 0; kk < 8; ++kk) {
            int k0 = half * 16 + 2 * kk;
            float t0, t1; upk2(t0, t1, accI[kk]);
            float u0, u1; upk2(u0, u1, accJ[kk]);
            s_ij = fmaf(fmaxf(t0, 0.0f), sW3[k0],     s_ij);
            s_ij = fmaf(fmaxf(t1, 0.0f), sW3[k0 + 1], s_ij);
            s_ji = fmaf(fmaxf(u0, 0.0f), sW3[k0],     s_ji);
            s_ji = fmaf(fmaxf(u1, 0.0f), sW3[k0 + 1], s_ji);
        }
    }
    float val = scale * (s_ij - s_ji);   // b3 cancels

    // --- block reduction over j ---
    #pragma unroll
    for (int off = 16; off > 0; off >>= 1)
        val += __shfl_xor_sync(0xffffffffu, val, off);
    if ((threadIdx.x & 31) == 0) sred[threadIdx.x >> 5] = val;
    __syncthreads();
    if (threadIdx.x == 0) {
        float t = 0.0f;
        #pragma unroll
        for (int w = 0; w < 8; ++w) t += sred[w];
        out[bi] = q[bi] + t;
    }
}

// ---------------------------------------------------------------------------
// Launch. Inputs (metadata order): h, e, x, q, mask, W1, b1, W2, b2, W3, b3.
// ---------------------------------------------------------------------------
extern "C" void kernel_launch(void* const* d_in, const int* in_sizes, int n_in,
                              void* d_out, int out_size)
{
    const float* h    = (const float*)d_in[0];
    const float* e    = (const float*)d_in[1];
    const float* x    = (const float*)d_in[2];
    const float* q    = (const float*)d_in[3];
    const float* mask = (const float*)d_in[4];
    const float* W1   = (const float*)d_in[5];
    const float* b1   = (const float*)d_in[6];
    const float* W2   = (const float*)d_in[7];
    const float* b2   = (const float*)d_in[8];
    const float* W3   = (const float*)d_in[9];
    // d_in[10] = b3: cancels in elec_ij - elec_ji.
    float* out = (float*)d_out;

    atom_proj_kernel<<<(NATOMS * H1C + 255) / 256, 256>>>(h, x, q, W1, b1);
    pair_kernel<<<NATOMS, 256>>>(e, mask, q, W1, W2, b2, W3, out);
}